// round 15
// baseline (speedup 1.0000x reference)
#include <cuda_runtime.h>
#include <cuda_bf16.h>
#include <math.h>
#include <stddef.h>
#include <stdint.h>

#define D_MODEL 1024
#define DK      1024
#define BATCH   4
#define SEQ     2048
#define BT      (BATCH * SEQ)

// ===========================================================================
// K-pair permutation (within each 8-column group along the K dimension):
//   logical j (0..7) -> phys 2*(j&3) + (j>>2)   [pairs (c, c+4) adjacent]
//   phys p -> logical (p>>1) + ((p&1)<<2)
// All GEMM operand tensors are stored K-permuted. f32 C outputs (mode 0) are
// plain; mode 1/2 outputs are operand tensors and get permuted columns.
// ===========================================================================
__device__ __host__ __forceinline__ int perm8(int j)  { return 2 * (j & 3) + (j >> 2); }
__device__ __host__ __forceinline__ int inv8(int p)   { return (p >> 1) + ((p & 1) << 2); }

__device__ float g_xt[(size_t)BT * D_MODEL];        // x, tf32-rounded, K-perm
__device__ float g_wt[3][(size_t)D_MODEL * DK];     // W^T, tf32-rounded, K-perm
__device__ float g_QKV[3][(size_t)BT * DK];         // Q,K,V tf32-rounded, K-perm (dk)
__device__ float g_Vt[(size_t)BATCH * DK * SEQ];    // V^T per batch, K-perm (seq)
__device__ float g_S[(size_t)BATCH * SEQ * SEQ];    // scores/P, K-perm (seq)

__device__ __forceinline__ uint32_t smem_to_u32(const void* p) {
    uint32_t a;
    asm("{ .reg .u64 t; cvta.to.shared.u64 t, %1; cvt.u32.u64 %0, t; }" : "=r"(a) : "l"(p));
    return a;
}
__device__ __forceinline__ float round_tf32(float f) {
    uint32_t r;
    asm("cvt.rna.tf32.f32 %0, %1;" : "=r"(r) : "f"(f));
    return __uint_as_float(r);
}
__device__ __forceinline__ void mma_tf32(float* c, const uint32_t* a, const uint32_t* b) {
    asm volatile("mma.sync.aligned.m16n8k8.row.col.f32.tf32.tf32.f32 "
                 "{%0,%1,%2,%3}, {%4,%5,%6,%7}, {%8,%9}, {%0,%1,%2,%3};"
                 : "+f"(c[0]), "+f"(c[1]), "+f"(c[2]), "+f"(c[3])
                 : "r"(a[0]), "r"(a[1]), "r"(a[2]), "r"(a[3]), "r"(b[0]), "r"(b[1]));
}

#define CP_ASYNC16(dst, src) \
    asm volatile("cp.async.cg.shared.global [%0], [%1], 16;" :: "r"(dst), "l"(src) : "memory")
#define CP_COMMIT() asm volatile("cp.async.commit_group;" ::: "memory")
#define CP_WAIT0()  asm volatile("cp.async.wait_group 0;" ::: "memory")
#define CP_WAIT1()  asm volatile("cp.async.wait_group 1;" ::: "memory")

// ===========================================================================
// x -> tf32-rounded, K-perm.  Each thread: 8 consecutive logical cols
// (one perm group), two float4 in, two float4 out (phys order l0,l4,l1,l5 | l2,l6,l3,l7)
// ===========================================================================
__global__ __launch_bounds__(256)
void round_kernel(const float* __restrict__ in, float* __restrict__ out)
{
    size_t i = ((size_t)blockIdx.x * 256 + threadIdx.x) * 8;
    float4 v0 = *(const float4*)(in + i);
    float4 v1 = *(const float4*)(in + i + 4);
    float l0 = round_tf32(v0.x), l1 = round_tf32(v0.y), l2 = round_tf32(v0.z), l3 = round_tf32(v0.w);
    float l4 = round_tf32(v1.x), l5 = round_tf32(v1.y), l6 = round_tf32(v1.z), l7 = round_tf32(v1.w);
    *(float4*)(out + i)     = make_float4(l0, l4, l1, l5);
    *(float4*)(out + i + 4) = make_float4(l2, l6, l3, l7);
}

// W (d_model, dk) -> W^T (dk, d_model), tf32-rounded, K-perm along d_model
__global__ __launch_bounds__(256)
void wt_round_kernel(const float* __restrict__ W, float* __restrict__ Wt)
{
    __shared__ float tile[32][33];
    int x = blockIdx.x * 32 + threadIdx.x;
    int y = blockIdx.y * 32 + threadIdx.y;
    #pragma unroll
    for (int i = 0; i < 32; i += 8)
        tile[threadIdx.y + i][threadIdx.x] = W[(size_t)(y + i) * DK + x];
    __syncthreads();
    int x2 = blockIdx.y * 32 + threadIdx.x;            // logical col along d_model
    int px = (x2 & ~7) | perm8(x2 & 7);
    int y2 = blockIdx.x * 32 + threadIdx.y;
    #pragma unroll
    for (int i = 0; i < 32; i += 8)
        Wt[(size_t)(y2 + i) * D_MODEL + px] = round_tf32(tile[threadIdx.x][threadIdx.y + i]);
}

// V (t, dk) -> V^T (dk, t) per batch, K-perm along seq
__global__ __launch_bounds__(256)
void v_transpose_kernel(const float* __restrict__ V, float* __restrict__ Vt)
{
    __shared__ float tile[32][33];
    const size_t in_base  = (size_t)blockIdx.z * SEQ * DK;
    const size_t out_base = (size_t)blockIdx.z * DK * SEQ;
    int n = blockIdx.x * 32 + threadIdx.x;
    int t = blockIdx.y * 32 + threadIdx.y;
    // V rows are K-permuted along dk (from QKV epilogue). Reading col n here
    // reads the PHYS col n; after transpose the dk index becomes the row,
    // where layout is irrelevant as long as A and B agree. PV's B rows are
    // indexed by dk: PV A (=P) rows are q (plain). D columns of PV = dk rows
    // of Vt: out[., col dk] must be PLAIN dk order. So un-permute n here.
    int nl = (n & ~7) | inv8(n & 7);   // logical dk of phys col n... (see note)
    #pragma unroll
    for (int i = 0; i < 32; i += 8)
        tile[threadIdx.y + i][threadIdx.x] = V[in_base + (size_t)(t + i) * DK + n];
    __syncthreads();
    int t2 = blockIdx.y * 32 + threadIdx.x;            // logical col along seq
    int pt = (t2 & ~7) | perm8(t2 & 7);
    int n2 = blockIdx.x * 32 + threadIdx.y;
    int n2l = (n2 & ~7) | inv8(n2 & 7);
    #pragma unroll
    for (int i = 0; i < 32; i += 8) {
        int nr = ((n2 + i) & ~7) | inv8((n2 + i) & 7); // logical dk row for phys col n2+i
        Vt[out_base + (size_t)nr * SEQ + pt] = tile[threadIdx.x][threadIdx.y + i];
    }
    (void)nl; (void)n2l;
}

// ===========================================================================
// tf32 GEMM, K-permuted operands: C = scale * (A @ B^T)
// 128x128 CTA, 256 thr, 8 warps (4Mx2N), warp 32x64, KC=32, 2-stage cp.async.
// mode 0: plain f32*scale; mode 1: tf32-rounded, K-perm cols; mode 2: f32*scale, K-perm cols
// ===========================================================================
#define STG_B   32768
#define T_B     16384
#define GEMM_SMEM (2 * STG_B)

__device__ __forceinline__ void load_stage(uint32_t st,
    const float* A, const float* B, int K, int bm, int bn, int k0, int tid)
{
    #pragma unroll
    for (int i = 0; i < 4; i++) {
        const int f  = tid + (i << 8);
        const int r  = f >> 3;
        const int ch = f & 7;
        const uint32_t so = (uint32_t)(r * 128 + ((ch ^ (r & 7)) << 4));
        CP_ASYNC16(st + so,       A + (size_t)(bm + r) * K + k0 + ch * 4);
        CP_ASYNC16(st + T_B + so, B + (size_t)(bn + r) * K + k0 + ch * 4);
    }
}

__global__ __launch_bounds__(256, 2)
void gemm_tf32(const float* __restrict__ A, const float* __restrict__ B,
               int K, size_t sA, size_t sB,
               int mode, float scale, int causal, int trik,
               float* __restrict__ C, int ldc, size_t sC)
{
    const int bm = blockIdx.y * 128;
    const int bn = blockIdx.x * 128;
    const int b  = blockIdx.z;
    if (causal && bn > bm + 127) return;

    A += (size_t)b * sA;
    B += (size_t)b * sB;

    extern __shared__ char smem[];
    const uint32_t sb = smem_to_u32(smem);
    (void)sb;

    const int tid  = threadIdx.x;
    const int lane = tid & 31;
    const int wid  = tid >> 5;
    const int wm   = wid & 3;
    const int wn   = wid >> 2;
    const int r4   = lane >> 2;      // 0..7
    const int c4   = lane & 3;       // 0..3

    float acc[2][8][4];
    #pragma unroll
    for (int mt = 0; mt < 2; mt++)
        #pragma unroll
        for (int nt = 0; nt < 8; nt++)
            #pragma unroll
            for (int j = 0; j < 4; j++) acc[mt][nt][j] = 0.0f;

    int Keff = trik ? (bm + 128 < K ? bm + 128 : K) : K;
    const int nc = Keff >> 5;

    {
        const uint32_t s0 = smem_to_u32(smem);
        load_stage(s0, A, B, K, bm, bn, 0, tid);
        CP_COMMIT();
    }

    for (int c = 0; c < nc; c++) {
        if (c + 1 < nc) {
            load_stage(smem_to_u32(smem) + ((c + 1) & 1) * STG_B, A, B, K, bm, bn, (c + 1) << 5, tid);
            CP_COMMIT();
            CP_WAIT1();
        } else {
            CP_WAIT0();
        }
        __syncthreads();

        const char* pA = smem + (c & 1) * STG_B;
        const char* pB = pA + T_B;

        #pragma unroll
        for (int ks = 0; ks < 4; ks++) {
            // phys pair base: cols (2*c4, 2*c4+1) within group ks
            // chunk = 2*ks + (c4>>1); inner byte = (c4&1)*8
            uint32_t af[2][4];
            uint32_t bf[8][2];
            #pragma unroll
            for (int mt = 0; mt < 2; mt++) {
                const int row0 = wm * 32 + mt * 16 + r4;
                const int row1 = row0 + 8;
                const int chnk = 2 * ks + (c4 >> 1);
                const uint32_t o0 = (uint32_t)(row0 * 128 + ((chnk ^ (row0 & 7)) << 4) + (c4 & 1) * 8);
                const uint32_t o1 = (uint32_t)(row1 * 128 + ((chnk ^ (row1 & 7)) << 4) + (c4 & 1) * 8);
                uint2 v0 = *(const uint2*)(pA + o0);   // (a0, a2)
                uint2 v1 = *(const uint2*)(pA + o1);   // (a1, a3)
                af[mt][0] = v0.x; af[mt][2] = v0.y;
                af[mt][1] = v1.x; af[mt][3] = v1.y;
            }
            #pragma unroll
            for (int nt = 0; nt < 8; nt++) {
                const int rn   = wn * 64 + nt * 8 + r4;
                const int chnk = 2 * ks + (c4 >> 1);
                const uint32_t o = (uint32_t)(rn * 128 + ((chnk ^ (rn & 7)) << 4) + (c4 & 1) * 8);
                uint2 v = *(const uint2*)(pB + o);     // (b0, b1)
                bf[nt][0] = v.x; bf[nt][1] = v.y;
            }
            #pragma unroll
            for (int mt = 0; mt < 2; mt++)
                #pragma unroll
                for (int nt = 0; nt < 8; nt++)
                    mma_tf32(acc[mt][nt], af[mt], bf[nt]);
        }
        __syncthreads();
    }

    // ---- epilogue ----
    const int tr = lane >> 2;
    const int tc = (lane & 3) * 2;
    float* Cb = C + (size_t)b * sC;
    #pragma unroll
    for (int mt = 0; mt < 2; mt++)
        #pragma unroll
        for (int nt = 0; nt < 8; nt++) {
            const int row = bm + wm * 32 + mt * 16 + tr;
            const int col = bn + wn * 64 + nt * 8 + tc;
            float v0 = acc[mt][nt][0] * scale, v1 = acc[mt][nt][1] * scale;
            float v2 = acc[mt][nt][2] * scale, v3 = acc[mt][nt][3] * scale;
            if (mode == 0) {
                *(float2*)&Cb[(size_t)row * ldc + col]       = make_float2(v0, v1);
                *(float2*)&Cb[(size_t)(row + 8) * ldc + col] = make_float2(v2, v3);
            } else {
                if (mode == 1) {
                    v0 = round_tf32(v0); v1 = round_tf32(v1);
                    v2 = round_tf32(v2); v3 = round_tf32(v3);
                }
                const int gb = col & ~7;
                const int p0 = gb | perm8(col & 7);
                const int p1 = gb | perm8((col + 1) & 7);
                Cb[(size_t)row * ldc + p0]       = v0;
                Cb[(size_t)row * ldc + p1]       = v1;
                Cb[(size_t)(row + 8) * ldc + p0] = v2;
                Cb[(size_t)(row + 8) * ldc + p1] = v3;
            }
        }
}

// ===========================================================================
// Causal softmax on K-permuted rows: mask by logical index, write tf32-rounded
// P in place (still K-permuted), zero tail to 128-aligned PV boundary.
// ===========================================================================
__global__ __launch_bounds__(256)
void softmax_causal_kernel()
{
    const int q = blockIdx.x;
    const int b = blockIdx.y;
    const size_t base = ((size_t)b * SEQ + q) * SEQ;
    float* row = g_S + base;
    const int len  = q + 1;
    const int wlen = ((q >> 7) + 1) << 7;

    const int tid = threadIdx.x, lane = tid & 31, w = tid >> 5;
    __shared__ float red_max[8], red_sum[8], s_m, s_inv;

    float m = -INFINITY;
    for (int j = tid; j < wlen; j += 256) {
        int jl = (j & ~7) | inv8(j & 7);
        if (jl < len) m = fmaxf(m, row[j]);
    }
    #pragma unroll
    for (int o = 16; o; o >>= 1) m = fmaxf(m, __shfl_xor_sync(0xffffffffu, m, o));
    if (lane == 0) red_max[w] = m;
    __syncthreads();
    if (w == 0) {
        float v = (lane < 8) ? red_max[lane] : -INFINITY;
        #pragma unroll
        for (int o = 4; o; o >>= 1) v = fmaxf(v, __shfl_xor_sync(0xffffffffu, v, o));
        if (lane == 0) s_m = v;
    }
    __syncthreads();
    m = s_m;

    float e[8];
    float s = 0.0f;
    {
        int idx = 0;
        for (int j = tid; j < wlen; j += 256, idx++) {
            int jl = (j & ~7) | inv8(j & 7);
            float v = (jl < len) ? __expf(row[j] - m) : 0.0f;
            e[idx] = v;
            s += v;
        }
    }
    #pragma unroll
    for (int o = 16; o; o >>= 1) s += __shfl_xor_sync(0xffffffffu, s, o);
    if (lane == 0) red_sum[w] = s;
    __syncthreads();
    if (w == 0) {
        float v = (lane < 8) ? red_sum[lane] : 0.0f;
        #pragma unroll
        for (int o = 4; o; o >>= 1) v += __shfl_xor_sync(0xffffffffu, v, o);
        if (lane == 0) s_inv = 1.0f / v;
    }
    __syncthreads();
    const float inv = s_inv;

    {
        int idx = 0;
        for (int j = tid; j < wlen; j += 256, idx++) {
            float p = e[idx];
            row[j] = (p > 0.0f) ? round_tf32(p * inv) : 0.0f;
        }
    }
}

// ===========================================================================
extern "C" void kernel_launch(void* const* d_in, const int* in_sizes, int n_in,
                              void* d_out, int out_size)
{
    const float* x  = (const float*)d_in[0];
    const float* Wq = (const float*)d_in[1];
    const float* Wk = (const float*)d_in[2];
    const float* Wv = (const float*)d_in[3];
    float* out = (float*)d_out;

    cudaFuncSetAttribute(gemm_tf32, cudaFuncAttributeMaxDynamicSharedMemorySize, GEMM_SMEM);

    float *xt, *wt, *qkv, *Vt, *Sp;
    cudaGetSymbolAddress((void**)&xt, g_xt);
    cudaGetSymbolAddress((void**)&wt, g_wt);
    cudaGetSymbolAddress((void**)&qkv, g_QKV);
    cudaGetSymbolAddress((void**)&Vt, g_Vt);
    cudaGetSymbolAddress((void**)&Sp, g_S);

    const size_t WSZ  = (size_t)D_MODEL * DK;
    const size_t QKVS = (size_t)BT * DK;

    // 1) round + permute x; W -> W^T rounded + permuted
    round_kernel<<<(BT * D_MODEL) / (256 * 8), 256>>>(x, xt);
    {
        dim3 g(DK / 32, D_MODEL / 32), blk(32, 8);
        wt_round_kernel<<<g, blk>>>(Wq, wt + 0 * WSZ);
        wt_round_kernel<<<g, blk>>>(Wk, wt + 1 * WSZ);
        wt_round_kernel<<<g, blk>>>(Wv, wt + 2 * WSZ);
    }

    // 2) merged QKV projection -> tf32-rounded, K-perm along dk (mode 1)
    {
        dim3 grid(DK / 128, BT / 128, 3);
        gemm_tf32<<<grid, 256, GEMM_SMEM>>>(xt, wt,
            D_MODEL, 0, WSZ, 1, 1.0f, 0, 0,
            qkv, DK, QKVS);
    }

    // 3) V^T per batch (un-permutes dk rows, permutes seq cols)
    {
        dim3 g(DK / 32, SEQ / 32, BATCH), blk(32, 8);
        v_transpose_kernel<<<g, blk>>>(qkv + 2 * QKVS, Vt);
    }

    // 4) scores = (1/32) Q @ K^T, causal skip -> f32, K-perm along seq (mode 2)
    {
        dim3 grid(SEQ / 128, SEQ / 128, BATCH);
        gemm_tf32<<<grid, 256, GEMM_SMEM>>>(qkv, qkv + QKVS,
            DK, (size_t)SEQ * DK, (size_t)SEQ * DK, 2, 1.0f / 32.0f, 1, 0,
            Sp, SEQ, (size_t)SEQ * SEQ);
    }

    // 5) causal softmax on permuted rows (in-place, tf32-rounded P)
    softmax_causal_kernel<<<dim3(SEQ, BATCH), 256>>>();

    // 6) out = P @ V (K truncated, plain f32 output, mode 0)
    {
        dim3 grid(DK / 128, SEQ / 128, BATCH);
        gemm_tf32<<<grid, 256, GEMM_SMEM>>>(Sp, Vt,
            SEQ, (size_t)SEQ * SEQ, (size_t)DK * SEQ, 0, 1.0f, 0, 1,
            out, DK, (size_t)SEQ * DK);
    }
}

// round 16
// speedup vs baseline: 1.3916x; 1.3916x over previous
#include <cuda_runtime.h>
#include <cuda_bf16.h>
#include <math.h>
#include <stddef.h>
#include <stdint.h>

#define D_MODEL 1024
#define DK      1024
#define BATCH   4
#define SEQ     2048
#define BT      (BATCH * SEQ)

// ===========================================================================
// Scratch (f32 everywhere; operands pre-rounded to tf32 bit pattern)
// ===========================================================================
__device__ float g_xt[(size_t)BT * D_MODEL];
__device__ float g_wt[3][(size_t)D_MODEL * DK];     // W^T (dk, d_model), tf32-rounded
__device__ float g_QKV[3][(size_t)BT * DK];         // tf32-rounded Q, K, V
__device__ float g_Vt[(size_t)BATCH * DK * SEQ];    // per batch (dk, t), tf32-rounded
__device__ float g_S[(size_t)BATCH * SEQ * SEQ];    // scores, then P (tf32-rounded)

__device__ __forceinline__ uint32_t smem_to_u32(const void* p) {
    uint32_t a;
    asm("{ .reg .u64 t; cvta.to.shared.u64 t, %1; cvt.u32.u64 %0, t; }" : "=r"(a) : "l"(p));
    return a;
}
__device__ __forceinline__ float round_tf32(float f) {
    uint32_t r;
    asm("cvt.rna.tf32.f32 %0, %1;" : "=r"(r) : "f"(f));
    return __uint_as_float(r);
}
// m16n8k8 tf32 MMA, fp32 accum
__device__ __forceinline__ void mma_tf32(float* c, const uint32_t* a, const uint32_t* b) {
    asm volatile("mma.sync.aligned.m16n8k8.row.col.f32.tf32.tf32.f32 "
                 "{%0,%1,%2,%3}, {%4,%5,%6,%7}, {%8,%9}, {%0,%1,%2,%3};"
                 : "+f"(c[0]), "+f"(c[1]), "+f"(c[2]), "+f"(c[3])
                 : "r"(a[0]), "r"(a[1]), "r"(a[2]), "r"(a[3]), "r"(b[0]), "r"(b[1]));
}
// ldmatrix x4: 4 8x8-b16 matrices; for tf32, each 8 rows x 16B = 8x4 f32 tile.
__device__ __forceinline__ void ldm_x4(uint32_t& r0, uint32_t& r1, uint32_t& r2, uint32_t& r3,
                                       uint32_t addr) {
    asm volatile("ldmatrix.sync.aligned.m8n8.x4.shared.b16 {%0,%1,%2,%3}, [%4];"
                 : "=r"(r0), "=r"(r1), "=r"(r2), "=r"(r3) : "r"(addr));
}

#define CP_ASYNC16(dst, src) \
    asm volatile("cp.async.cg.shared.global [%0], [%1], 16;" :: "r"(dst), "l"(src) : "memory")
#define CP_COMMIT() asm volatile("cp.async.commit_group;" ::: "memory")
#define CP_WAIT0()  asm volatile("cp.async.wait_group 0;" ::: "memory")
#define CP_WAIT1()  asm volatile("cp.async.wait_group 1;" ::: "memory")

// ===========================================================================
// x (f32) -> tf32-rounded copy
// ===========================================================================
__global__ __launch_bounds__(256)
void round_kernel(const float* __restrict__ in, float* __restrict__ out)
{
    size_t i = ((size_t)blockIdx.x * 256 + threadIdx.x) * 4;
    float4 v = *(const float4*)(in + i);
    v.x = round_tf32(v.x); v.y = round_tf32(v.y);
    v.z = round_tf32(v.z); v.w = round_tf32(v.w);
    *(float4*)(out + i) = v;
}

// W (d_model, dk) -> W^T (dk, d_model), tf32-rounded
__global__ __launch_bounds__(256)
void wt_round_kernel(const float* __restrict__ W, float* __restrict__ Wt)
{
    __shared__ float tile[32][33];
    int x = blockIdx.x * 32 + threadIdx.x;
    int y = blockIdx.y * 32 + threadIdx.y;
    #pragma unroll
    for (int i = 0; i < 32; i += 8)
        tile[threadIdx.y + i][threadIdx.x] = W[(size_t)(y + i) * DK + x];
    __syncthreads();
    int x2 = blockIdx.y * 32 + threadIdx.x;
    int y2 = blockIdx.x * 32 + threadIdx.y;
    #pragma unroll
    for (int i = 0; i < 32; i += 8)
        Wt[(size_t)(y2 + i) * D_MODEL + x2] = round_tf32(tile[threadIdx.x][threadIdx.y + i]);
}

// V (t, dk) -> V^T (dk, t) per batch (values already rounded)
__global__ __launch_bounds__(256)
void v_transpose_kernel(const float* __restrict__ V, float* __restrict__ Vt)
{
    __shared__ float tile[32][33];
    const size_t in_base  = (size_t)blockIdx.z * SEQ * DK;
    const size_t out_base = (size_t)blockIdx.z * DK * SEQ;
    int n = blockIdx.x * 32 + threadIdx.x;
    int t = blockIdx.y * 32 + threadIdx.y;
    #pragma unroll
    for (int i = 0; i < 32; i += 8)
        tile[threadIdx.y + i][threadIdx.x] = V[in_base + (size_t)(t + i) * DK + n];
    __syncthreads();
    int t2 = blockIdx.y * 32 + threadIdx.x;
    int n2 = blockIdx.x * 32 + threadIdx.y;
    #pragma unroll
    for (int i = 0; i < 32; i += 8)
        Vt[out_base + (size_t)(n2 + i) * SEQ + t2] = tile[threadIdx.x][threadIdx.y + i];
}

// ===========================================================================
// tf32 GEMM: C[M,N] = scale * (A @ B^T)  (A: M x K row-major, B: N x K row-major)
// 128x128 CTA tile, 256 threads, 8 warps (4xM, 2xN), warp tile 32x64,
// KC=32, 2-stage cp.async, 2 CTAs/SM.  Fragment loads via ldmatrix.x4.
// mode 0: C = f32 * scale;  mode 1: C = tf32-rounded (f32 * scale)
// causal: skip CTA if bn > bm+127;  trik: K limited to bm+128.
// ===========================================================================
#define STG_B   32768   // A 16KB + B 16KB per stage
#define T_B     16384
#define GEMM_SMEM (2 * STG_B)

__device__ __forceinline__ void load_stage(uint32_t st,
    const float* A, const float* B, int K, int bm, int bn, int k0, int tid)
{
    #pragma unroll
    for (int i = 0; i < 4; i++) {
        const int f  = tid + (i << 8);      // 0..1023
        const int r  = f >> 3;              // row 0..127
        const int ch = f & 7;               // 16B chunk 0..7
        const uint32_t so = (uint32_t)(r * 128 + ((ch ^ (r & 7)) << 4));
        CP_ASYNC16(st + so,       A + (size_t)(bm + r) * K + k0 + ch * 4);
        CP_ASYNC16(st + T_B + so, B + (size_t)(bn + r) * K + k0 + ch * 4);
    }
}

__global__ __launch_bounds__(256, 2)
void gemm_tf32(const float* __restrict__ A, const float* __restrict__ B,
               int K, size_t sA, size_t sB,
               int mode, float scale, int causal, int trik,
               float* __restrict__ C, int ldc, size_t sC)
{
    const int bm = blockIdx.y * 128;
    const int bn = blockIdx.x * 128;
    const int b  = blockIdx.z;
    if (causal && bn > bm + 127) return;

    A += (size_t)b * sA;
    B += (size_t)b * sB;

    extern __shared__ char smem[];
    const uint32_t sb = smem_to_u32(smem);

    const int tid  = threadIdx.x;
    const int lane = tid & 31;
    const int wid  = tid >> 5;
    const int wm   = wid & 3;        // 0..3 -> 32-row slice
    const int wn   = wid >> 2;       // 0..1 -> 64-col slice

    // ldmatrix addressing: lane -> (sub = lane>>3, l7 = lane&7)
    const int l7  = lane & 7;
    const int sub = lane >> 3;
    // A: matrices {rows g, rows g+8} x {chunk 2ks, 2ks+1}
    const int rowA  = wm * 32 + l7 + ((sub & 1) << 3);   // + mt*16
    const int chA   = sub >> 1;                           // + 2ks
    // B: matrices {nt pair rows} x {chunk 2ks, 2ks+1}
    const int rowB  = wn * 64 + l7 + ((sub >> 1) << 3);  // + u*16
    const int chB   = sub & 1;                            // + 2ks

    float acc[2][8][4];
    #pragma unroll
    for (int mt = 0; mt < 2; mt++)
        #pragma unroll
        for (int nt = 0; nt < 8; nt++)
            #pragma unroll
            for (int j = 0; j < 4; j++) acc[mt][nt][j] = 0.0f;

    int Keff = trik ? (bm + 128 < K ? bm + 128 : K) : K;
    const int nc = Keff >> 5;

    load_stage(sb, A, B, K, bm, bn, 0, tid);
    CP_COMMIT();

    for (int c = 0; c < nc; c++) {
        if (c + 1 < nc) {
            load_stage(sb + ((c + 1) & 1) * STG_B, A, B, K, bm, bn, (c + 1) << 5, tid);
            CP_COMMIT();
            CP_WAIT1();
        } else {
            CP_WAIT0();
        }
        __syncthreads();

        const uint32_t aA = sb + (c & 1) * STG_B;
        const uint32_t aB = aA + T_B;

        #pragma unroll
        for (int ks = 0; ks < 4; ks++) {
            uint32_t af[2][4], bf[8][2];
            // A fragments: 1 ldmatrix.x4 per m-tile
            #pragma unroll
            for (int mt = 0; mt < 2; mt++) {
                const int r  = rowA + mt * 16;
                const uint32_t ad = aA + (uint32_t)(r * 128 + (((2 * ks + chA) ^ l7) << 4));
                ldm_x4(af[mt][0], af[mt][1], af[mt][2], af[mt][3], ad);
            }
            // B fragments: 1 ldmatrix.x4 per pair of n-tiles
            #pragma unroll
            for (int u = 0; u < 4; u++) {
                const int r  = rowB + u * 16;
                const uint32_t ad = aB + (uint32_t)(r * 128 + (((2 * ks + chB) ^ l7) << 4));
                ldm_x4(bf[2*u][0], bf[2*u][1], bf[2*u+1][0], bf[2*u+1][1], ad);
            }
            #pragma unroll
            for (int mt = 0; mt < 2; mt++)
                #pragma unroll
                for (int nt = 0; nt < 8; nt++)
                    mma_tf32(acc[mt][nt], af[mt], bf[nt]);
        }
        __syncthreads();
    }

    // ---- epilogue ----
    const int tr = lane >> 2;
    const int tc = (lane & 3) * 2;
    float* Cb = C + (size_t)b * sC;
    #pragma unroll
    for (int mt = 0; mt < 2; mt++)
        #pragma unroll
        for (int nt = 0; nt < 8; nt++) {
            const int row = bm + wm * 32 + mt * 16 + tr;
            const int col = bn + wn * 64 + nt * 8 + tc;
            float v0 = acc[mt][nt][0] * scale, v1 = acc[mt][nt][1] * scale;
            float v2 = acc[mt][nt][2] * scale, v3 = acc[mt][nt][3] * scale;
            if (mode == 1) {
                v0 = round_tf32(v0); v1 = round_tf32(v1);
                v2 = round_tf32(v2); v3 = round_tf32(v3);
            }
            *(float2*)&Cb[(size_t)row * ldc + col]       = make_float2(v0, v1);
            *(float2*)&Cb[(size_t)(row + 8) * ldc + col] = make_float2(v2, v3);
        }
}

// ===========================================================================
// Causal softmax: in-place on g_S; writes tf32-rounded P, zero tail to
// the 128-aligned PV read boundary.
// ===========================================================================
__global__ __launch_bounds__(256)
void softmax_causal_kernel()
{
    const int q = blockIdx.x;
    const int b = blockIdx.y;
    const size_t base = ((size_t)b * SEQ + q) * SEQ;
    float* row = g_S + base;
    const int len  = q + 1;
    const int wlen = ((q >> 7) + 1) << 7;

    const int tid = threadIdx.x, lane = tid & 31, w = tid >> 5;
    __shared__ float red_max[8], red_sum[8], s_m, s_inv;

    float m = -INFINITY;
    for (int j = tid; j < len; j += 256) m = fmaxf(m, row[j]);
    #pragma unroll
    for (int o = 16; o; o >>= 1) m = fmaxf(m, __shfl_xor_sync(0xffffffffu, m, o));
    if (lane == 0) red_max[w] = m;
    __syncthreads();
    if (w == 0) {
        float v = (lane < 8) ? red_max[lane] : -INFINITY;
        #pragma unroll
        for (int o = 4; o; o >>= 1) v = fmaxf(v, __shfl_xor_sync(0xffffffffu, v, o));
        if (lane == 0) s_m = v;
    }
    __syncthreads();
    m = s_m;

    float e[8];
    float s = 0.0f;
    {
        int idx = 0;
        for (int j = tid; j < len; j += 256, idx++) { e[idx] = __expf(row[j] - m); s += e[idx]; }
    }
    #pragma unroll
    for (int o = 16; o; o >>= 1) s += __shfl_xor_sync(0xffffffffu, s, o);
    if (lane == 0) red_sum[w] = s;
    __syncthreads();
    if (w == 0) {
        float v = (lane < 8) ? red_sum[lane] : 0.0f;
        #pragma unroll
        for (int o = 4; o; o >>= 1) v += __shfl_xor_sync(0xffffffffu, v, o);
        if (lane == 0) s_inv = 1.0f / v;
    }
    __syncthreads();
    const float inv = s_inv;

    {
        int idx = 0;
        for (int j = tid; j < wlen; j += 256) {
            float p;
            if (j < len) { p = round_tf32(e[idx] * inv); idx++; } else p = 0.0f;
            row[j] = p;
        }
    }
}

// ===========================================================================
extern "C" void kernel_launch(void* const* d_in, const int* in_sizes, int n_in,
                              void* d_out, int out_size)
{
    const float* x  = (const float*)d_in[0];
    const float* Wq = (const float*)d_in[1];
    const float* Wk = (const float*)d_in[2];
    const float* Wv = (const float*)d_in[3];
    float* out = (float*)d_out;

    cudaFuncSetAttribute(gemm_tf32, cudaFuncAttributeMaxDynamicSharedMemorySize, GEMM_SMEM);

    float *xt, *wt, *qkv, *Vt, *Sp;
    cudaGetSymbolAddress((void**)&xt, g_xt);
    cudaGetSymbolAddress((void**)&wt, g_wt);
    cudaGetSymbolAddress((void**)&qkv, g_QKV);
    cudaGetSymbolAddress((void**)&Vt, g_Vt);
    cudaGetSymbolAddress((void**)&Sp, g_S);

    const size_t WSZ  = (size_t)D_MODEL * DK;
    const size_t QKVS = (size_t)BT * DK;

    // 1) round x to tf32; W -> W^T rounded
    round_kernel<<<(BT * D_MODEL) / (256 * 4), 256>>>(x, xt);
    {
        dim3 g(DK / 32, D_MODEL / 32), blk(32, 8);
        wt_round_kernel<<<g, blk>>>(Wq, wt + 0 * WSZ);
        wt_round_kernel<<<g, blk>>>(Wk, wt + 1 * WSZ);
        wt_round_kernel<<<g, blk>>>(Wv, wt + 2 * WSZ);
    }

    // 2) merged QKV projection (z selects W and output slice), tf32-rounded out
    {
        dim3 grid(DK / 128, BT / 128, 3);
        gemm_tf32<<<grid, 256, GEMM_SMEM>>>(xt, wt,
            D_MODEL, 0, WSZ, 1, 1.0f, 0, 0,
            qkv, DK, QKVS);
    }

    // 3) V^T per batch
    {
        dim3 g(DK / 32, SEQ / 32, BATCH), blk(32, 8);
        v_transpose_kernel<<<g, blk>>>(qkv + 2 * QKVS, Vt);
    }

    // 4) scores = (1/32) Q @ K^T, causal skip
    {
        dim3 grid(SEQ / 128, SEQ / 128, BATCH);
        gemm_tf32<<<grid, 256, GEMM_SMEM>>>(qkv, qkv + QKVS,
            DK, (size_t)SEQ * DK, (size_t)SEQ * DK, 0, 1.0f / 32.0f, 1, 0,
            Sp, SEQ, (size_t)SEQ * SEQ);
    }

    // 5) causal softmax (in-place, tf32-rounded P)
    softmax_causal_kernel<<<dim3(SEQ, BATCH), 256>>>();

    // 6) out = P @ V (K truncated per diagonal)
    {
        dim3 grid(DK / 128, SEQ / 128, BATCH);
        gemm_tf32<<<grid, 256, GEMM_SMEM>>>(Sp, Vt,
            SEQ, (size_t)SEQ * SEQ, (size_t)DK * SEQ, 0, 1.0f, 0, 1,
            out, DK, (size_t)SEQ * DK);
    }
}

// round 17
// speedup vs baseline: 1.4196x; 1.0201x over previous
#include <cuda_runtime.h>
#include <cuda_bf16.h>
#include <math.h>
#include <stddef.h>
#include <stdint.h>

#define D_MODEL 1024
#define DK      1024
#define BATCH   4
#define SEQ     2048
#define BT      (BATCH * SEQ)

// ===========================================================================
// Scratch (f32; operands pre-rounded to tf32 bit pattern)
// ===========================================================================
__device__ float g_xt[(size_t)BT * D_MODEL];
__device__ float g_wt[3][(size_t)D_MODEL * DK];     // W^T (dk, d_model), tf32-rounded
__device__ float g_QKV[3][(size_t)BT * DK];         // tf32-rounded Q, K, V
__device__ float g_Vt[(size_t)BATCH * DK * SEQ];    // per batch (dk, t)
__device__ float g_S[(size_t)BATCH * SEQ * SEQ];    // scores, then P

__device__ __forceinline__ uint32_t smem_to_u32(const void* p) {
    uint32_t a;
    asm("{ .reg .u64 t; cvta.to.shared.u64 t, %1; cvt.u32.u64 %0, t; }" : "=r"(a) : "l"(p));
    return a;
}
__device__ __forceinline__ float round_tf32(float f) {
    uint32_t r;
    asm("cvt.rna.tf32.f32 %0, %1;" : "=r"(r) : "f"(f));
    return __uint_as_float(r);
}
__device__ __forceinline__ void mma_tf32(float* c, const uint32_t* a, const uint32_t* b) {
    asm volatile("mma.sync.aligned.m16n8k8.row.col.f32.tf32.tf32.f32 "
                 "{%0,%1,%2,%3}, {%4,%5,%6,%7}, {%8,%9}, {%0,%1,%2,%3};"
                 : "+f"(c[0]), "+f"(c[1]), "+f"(c[2]), "+f"(c[3])
                 : "r"(a[0]), "r"(a[1]), "r"(a[2]), "r"(a[3]), "r"(b[0]), "r"(b[1]));
}
__device__ __forceinline__ void ldm_x4(uint32_t& r0, uint32_t& r1, uint32_t& r2, uint32_t& r3,
                                       uint32_t addr) {
    asm volatile("ldmatrix.sync.aligned.m8n8.x4.shared.b16 {%0,%1,%2,%3}, [%4];"
                 : "=r"(r0), "=r"(r1), "=r"(r2), "=r"(r3) : "r"(addr));
}

#define CP_ASYNC16(dst, src) \
    asm volatile("cp.async.cg.shared.global [%0], [%1], 16;" :: "r"(dst), "l"(src) : "memory")
#define CP_COMMIT() asm volatile("cp.async.commit_group;" ::: "memory")
#define CP_WAIT0()  asm volatile("cp.async.wait_group 0;" ::: "memory")
#define CP_WAIT1()  asm volatile("cp.async.wait_group 1;" ::: "memory")

// ===========================================================================
// x (f32) -> tf32-rounded copy
// ===========================================================================
__global__ __launch_bounds__(256)
void round_kernel(const float* __restrict__ in, float* __restrict__ out)
{
    size_t i = ((size_t)blockIdx.x * 256 + threadIdx.x) * 4;
    float4 v = *(const float4*)(in + i);
    v.x = round_tf32(v.x); v.y = round_tf32(v.y);
    v.z = round_tf32(v.z); v.w = round_tf32(v.w);
    *(float4*)(out + i) = v;
}

// W (d_model, dk) -> W^T (dk, d_model), tf32-rounded; z selects Wq/Wk/Wv
__global__ __launch_bounds__(256)
void wt_round_kernel(const float* __restrict__ Wq, const float* __restrict__ Wk,
                     const float* __restrict__ Wv, float* __restrict__ WtBase)
{
    const float* W = (blockIdx.z == 0) ? Wq : (blockIdx.z == 1) ? Wk : Wv;
    float* Wt = WtBase + (size_t)blockIdx.z * D_MODEL * DK;
    __shared__ float tile[32][33];
    int x = blockIdx.x * 32 + threadIdx.x;
    int y = blockIdx.y * 32 + threadIdx.y;
    #pragma unroll
    for (int i = 0; i < 32; i += 8)
        tile[threadIdx.y + i][threadIdx.x] = W[(size_t)(y + i) * DK + x];
    __syncthreads();
    int x2 = blockIdx.y * 32 + threadIdx.x;
    int y2 = blockIdx.x * 32 + threadIdx.y;
    #pragma unroll
    for (int i = 0; i < 32; i += 8)
        Wt[(size_t)(y2 + i) * D_MODEL + x2] = round_tf32(tile[threadIdx.x][threadIdx.y + i]);
}

// V (t, dk) -> V^T (dk, t) per batch
__global__ __launch_bounds__(256)
void v_transpose_kernel(const float* __restrict__ V, float* __restrict__ Vt)
{
    __shared__ float tile[32][33];
    const size_t in_base  = (size_t)blockIdx.z * SEQ * DK;
    const size_t out_base = (size_t)blockIdx.z * DK * SEQ;
    int n = blockIdx.x * 32 + threadIdx.x;
    int t = blockIdx.y * 32 + threadIdx.y;
    #pragma unroll
    for (int i = 0; i < 32; i += 8)
        tile[threadIdx.y + i][threadIdx.x] = V[in_base + (size_t)(t + i) * DK + n];
    __syncthreads();
    int t2 = blockIdx.y * 32 + threadIdx.x;
    int n2 = blockIdx.x * 32 + threadIdx.y;
    #pragma unroll
    for (int i = 0; i < 32; i += 8)
        Vt[out_base + (size_t)(n2 + i) * SEQ + t2] = tile[threadIdx.x][threadIdx.y + i];
}

// ===========================================================================
// tf32 GEMM: C[M,N] = scale * (A @ B^T)
// 128x128 CTA tile, 256 threads, 8 warps (4xM, 2xN), warp tile 32x64,
// KC=32, 3-stage cp.async ring, SINGLE __syncthreads per chunk, 2 CTAs/SM.
// ldmatrix.x4 fragment loads. mode 0: f32*scale; mode 1: tf32-rounded.
// causal: skip CTA if bn > bm+127; trik: K = bm+128 + heavy-tile-first order.
// ===========================================================================
#define STG_B   32768   // A 16KB + B 16KB per stage
#define T_B     16384
#define GEMM_SMEM (3 * STG_B)

__device__ __forceinline__ void load_stage(uint32_t st,
    const float* A, const float* B, int K, int bm, int bn, int k0, int tid)
{
    #pragma unroll
    for (int i = 0; i < 4; i++) {
        const int f  = tid + (i << 8);
        const int r  = f >> 3;
        const int ch = f & 7;
        const uint32_t so = (uint32_t)(r * 128 + ((ch ^ (r & 7)) << 4));
        CP_ASYNC16(st + so,       A + (size_t)(bm + r) * K + k0 + ch * 4);
        CP_ASYNC16(st + T_B + so, B + (size_t)(bn + r) * K + k0 + ch * 4);
    }
}

__global__ __launch_bounds__(256, 2)
void gemm_tf32(const float* __restrict__ A, const float* __restrict__ B,
               int K, size_t sA, size_t sB,
               int mode, float scale, int causal, int trik,
               float* __restrict__ C, int ldc, size_t sC)
{
    const int by = trik ? ((int)gridDim.y - 1 - (int)blockIdx.y) : (int)blockIdx.y;
    const int bm = by * 128;
    const int bn = blockIdx.x * 128;
    const int b  = blockIdx.z;
    if (causal && bn > bm + 127) return;

    A += (size_t)b * sA;
    B += (size_t)b * sB;

    extern __shared__ char smem[];
    const uint32_t sb = smem_to_u32(smem);

    const int tid  = threadIdx.x;
    const int lane = tid & 31;
    const int wid  = tid >> 5;
    const int wm   = wid & 3;
    const int wn   = wid >> 2;

    const int l7  = lane & 7;
    const int sub = lane >> 3;
    const int rowA = wm * 32 + l7 + ((sub & 1) << 3);   // + mt*16
    const int chA  = sub >> 1;                           // + 2ks
    const int rowB = wn * 64 + l7 + ((sub >> 1) << 3);  // + u*16
    const int chB  = sub & 1;                            // + 2ks

    float acc[2][8][4];
    #pragma unroll
    for (int mt = 0; mt < 2; mt++)
        #pragma unroll
        for (int nt = 0; nt < 8; nt++)
            #pragma unroll
            for (int j = 0; j < 4; j++) acc[mt][nt][j] = 0.0f;

    int Keff = trik ? (bm + 128 < K ? bm + 128 : K) : K;
    const int nc = Keff >> 5;   // always >= 4

    load_stage(sb + 0 * STG_B, A, B, K, bm, bn, 0, tid);
    CP_COMMIT();
    load_stage(sb + 1 * STG_B, A, B, K, bm, bn, 32, tid);
    CP_COMMIT();

    int buf = 0;
    for (int c = 0; c < nc; c++) {
        if (c + 1 < nc) CP_WAIT1(); else CP_WAIT0();
        __syncthreads();   // single barrier per chunk; also retires buf (c+2)%3

        if (c + 2 < nc) {
            int nb = buf + 2; if (nb >= 3) nb -= 3;
            load_stage(sb + nb * STG_B, A, B, K, bm, bn, (c + 2) << 5, tid);
            CP_COMMIT();
        }

        const uint32_t aA = sb + buf * STG_B;
        const uint32_t aB = aA + T_B;

        #pragma unroll
        for (int ks = 0; ks < 4; ks++) {
            uint32_t af[2][4], bf[8][2];
            #pragma unroll
            for (int mt = 0; mt < 2; mt++) {
                const int r  = rowA + mt * 16;
                const uint32_t ad = aA + (uint32_t)(r * 128 + (((2 * ks + chA) ^ l7) << 4));
                ldm_x4(af[mt][0], af[mt][1], af[mt][2], af[mt][3], ad);
            }
            #pragma unroll
            for (int u = 0; u < 4; u++) {
                const int r  = rowB + u * 16;
                const uint32_t ad = aB + (uint32_t)(r * 128 + (((2 * ks + chB) ^ l7) << 4));
                ldm_x4(bf[2*u][0], bf[2*u][1], bf[2*u+1][0], bf[2*u+1][1], ad);
            }
            #pragma unroll
            for (int mt = 0; mt < 2; mt++)
                #pragma unroll
                for (int nt = 0; nt < 8; nt++)
                    mma_tf32(acc[mt][nt], af[mt], bf[nt]);
        }

        buf = (buf == 2) ? 0 : buf + 1;
    }

    // ---- epilogue ----
    const int tr = lane >> 2;
    const int tc = (lane & 3) * 2;
    float* Cb = C + (size_t)b * sC;
    #pragma unroll
    for (int mt = 0; mt < 2; mt++)
        #pragma unroll
        for (int nt = 0; nt < 8; nt++) {
            const int row = bm + wm * 32 + mt * 16 + tr;
            const int col = bn + wn * 64 + nt * 8 + tc;
            float v0 = acc[mt][nt][0] * scale, v1 = acc[mt][nt][1] * scale;
            float v2 = acc[mt][nt][2] * scale, v3 = acc[mt][nt][3] * scale;
            if (mode == 1) {
                v0 = round_tf32(v0); v1 = round_tf32(v1);
                v2 = round_tf32(v2); v3 = round_tf32(v3);
            }
            *(float2*)&Cb[(size_t)row * ldc + col]       = make_float2(v0, v1);
            *(float2*)&Cb[(size_t)(row + 8) * ldc + col] = make_float2(v2, v3);
        }
}

// ===========================================================================
// Causal softmax: in-place on g_S; tf32-rounded P, zero tail to the
// 128-aligned PV read boundary.
// ===========================================================================
__global__ __launch_bounds__(256)
void softmax_causal_kernel()
{
    const int q = blockIdx.x;
    const int b = blockIdx.y;
    const size_t base = ((size_t)b * SEQ + q) * SEQ;
    float* row = g_S + base;
    const int len  = q + 1;
    const int wlen = ((q >> 7) + 1) << 7;

    const int tid = threadIdx.x, lane = tid & 31, w = tid >> 5;
    __shared__ float red_max[8], red_sum[8], s_m, s_inv;

    float m = -INFINITY;
    for (int j = tid; j < len; j += 256) m = fmaxf(m, row[j]);
    #pragma unroll
    for (int o = 16; o; o >>= 1) m = fmaxf(m, __shfl_xor_sync(0xffffffffu, m, o));
    if (lane == 0) red_max[w] = m;
    __syncthreads();
    if (w == 0) {
        float v = (lane < 8) ? red_max[lane] : -INFINITY;
        #pragma unroll
        for (int o = 4; o; o >>= 1) v = fmaxf(v, __shfl_xor_sync(0xffffffffu, v, o));
        if (lane == 0) s_m = v;
    }
    __syncthreads();
    m = s_m;

    float e[8];
    float s = 0.0f;
    {
        int idx = 0;
        for (int j = tid; j < len; j += 256, idx++) { e[idx] = __expf(row[j] - m); s += e[idx]; }
    }
    #pragma unroll
    for (int o = 16; o; o >>= 1) s += __shfl_xor_sync(0xffffffffu, s, o);
    if (lane == 0) red_sum[w] = s;
    __syncthreads();
    if (w == 0) {
        float v = (lane < 8) ? red_sum[lane] : 0.0f;
        #pragma unroll
        for (int o = 4; o; o >>= 1) v += __shfl_xor_sync(0xffffffffu, v, o);
        if (lane == 0) s_inv = 1.0f / v;
    }
    __syncthreads();
    const float inv = s_inv;

    {
        int idx = 0;
        for (int j = tid; j < wlen; j += 256) {
            float p;
            if (j < len) { p = round_tf32(e[idx] * inv); idx++; } else p = 0.0f;
            row[j] = p;
        }
    }
}

// ===========================================================================
extern "C" void kernel_launch(void* const* d_in, const int* in_sizes, int n_in,
                              void* d_out, int out_size)
{
    const float* x  = (const float*)d_in[0];
    const float* Wq = (const float*)d_in[1];
    const float* Wk = (const float*)d_in[2];
    const float* Wv = (const float*)d_in[3];
    float* out = (float*)d_out;

    cudaFuncSetAttribute(gemm_tf32, cudaFuncAttributeMaxDynamicSharedMemorySize, GEMM_SMEM);

    float *xt, *wt, *qkv, *Vt, *Sp;
    cudaGetSymbolAddress((void**)&xt, g_xt);
    cudaGetSymbolAddress((void**)&wt, g_wt);
    cudaGetSymbolAddress((void**)&qkv, g_QKV);
    cudaGetSymbolAddress((void**)&Vt, g_Vt);
    cudaGetSymbolAddress((void**)&Sp, g_S);

    const size_t WSZ  = (size_t)D_MODEL * DK;
    const size_t QKVS = (size_t)BT * DK;

    // 1) round x; W -> W^T rounded (one launch, z selects matrix)
    round_kernel<<<(BT * D_MODEL) / (256 * 4), 256>>>(x, xt);
    {
        dim3 g(DK / 32, D_MODEL / 32, 3), blk(32, 8);
        wt_round_kernel<<<g, blk>>>(Wq, Wk, Wv, wt);
    }

    // 2) merged QKV projection, tf32-rounded out
    {
        dim3 grid(DK / 128, BT / 128, 3);
        gemm_tf32<<<grid, 256, GEMM_SMEM>>>(xt, wt,
            D_MODEL, 0, WSZ, 1, 1.0f, 0, 0,
            qkv, DK, QKVS);
    }

    // 3) V^T per batch
    {
        dim3 g(DK / 32, SEQ / 32, BATCH), blk(32, 8);
        v_transpose_kernel<<<g, blk>>>(qkv + 2 * QKVS, Vt);
    }

    // 4) scores = (1/32) Q @ K^T, causal skip
    {
        dim3 grid(SEQ / 128, SEQ / 128, BATCH);
        gemm_tf32<<<grid, 256, GEMM_SMEM>>>(qkv, qkv + QKVS,
            DK, (size_t)SEQ * DK, (size_t)SEQ * DK, 0, 1.0f / 32.0f, 1, 0,
            Sp, SEQ, (size_t)SEQ * SEQ);
    }

    // 5) causal softmax (in-place, tf32-rounded P)
    softmax_causal_kernel<<<dim3(SEQ, BATCH), 256>>>();

    // 6) out = P @ V (K truncated per diagonal, heavy tiles first)
    {
        dim3 grid(DK / 128, SEQ / 128, BATCH);
        gemm_tf32<<<grid, 256, GEMM_SMEM>>>(Sp, Vt,
            SEQ, (size_t)SEQ * SEQ, (size_t)DK * SEQ, 0, 1.0f, 0, 1,
            out, DK, (size_t)SEQ * DK);
    }
}